// round 3
// baseline (speedup 1.0000x reference)
#include <cuda_runtime.h>

// PointAttentionEncoder1D: P points, K=16 neighbors.
// MLPs: 6x (3->16->32, leaky 0.01), weight_process 32->64->32 (leaky 0.01).
// Vector attention: softmax over channel dim, sum over neighbors.
// Strategy: 1 thread per point, weights in shared (broadcast LDS), fp32.

constexpr int KNB = 16;   // neighbors per point

// ---- small MLP 3 -> 16 -> 32 with leaky relu on hidden ----
__device__ __forceinline__ void mlp3_16_32(
    const float* __restrict__ w1,   // [3][16]   (shared)
    const float* __restrict__ b1,   // [16]
    const float* __restrict__ w2,   // [16][32]
    const float* __restrict__ b2,   // [32]
    float x0, float x1, float x2,
    float* __restrict__ o)          // [32] (registers, static indices only)
{
    float h[16];
#pragma unroll
    for (int i = 0; i < 16; i++) {
        float v = b1[i] + x0 * w1[i] + x1 * w1[16 + i] + x2 * w1[32 + i];
        h[i] = v > 0.f ? v : 0.01f * v;
    }
#pragma unroll
    for (int c = 0; c < 32; c++) o[c] = b2[c];
    // keep this loop rolled (code size); h[] goes to local (L1-hot), fine.
#pragma unroll 1
    for (int i = 0; i < 16; i++) {
        float hi = h[i];
        const float* w2r = w2 + i * 32;
#pragma unroll
        for (int c = 0; c < 32; c++) o[c] += hi * w2r[c];
    }
}

__global__ void __launch_bounds__(128)
pae_kernel(const float* __restrict__ center,   // [P,1,3]
           const float* __restrict__ other,    // [P,K,3]
           const float* __restrict__ mw1,      // [6,3,16]
           const float* __restrict__ mb1,      // [6,16]
           const float* __restrict__ mw2,      // [6,16,32]
           const float* __restrict__ mb2,      // [6,32]
           const float* __restrict__ ww1,      // [32,64]
           const float* __restrict__ wb1,      // [64]
           const float* __restrict__ ww2,      // [64,32]
           const float* __restrict__ wb2,      // [32]
           float* __restrict__ out,            // [P,32]
           int P)
{
    __shared__ float s_mw1[6 * 3 * 16];
    __shared__ float s_mb1[6 * 16];
    __shared__ float s_mw2[6 * 16 * 32];
    __shared__ float s_mb2[6 * 32];
    __shared__ float s_w1t[64 * 32];   // transposed wp_w1: [m][c]
    __shared__ float s_wb1[64];
    __shared__ float s_w2[64 * 32];    // wp_w2 as-is: [m][c]
    __shared__ float s_wb2[32];

    const int tid = threadIdx.x;
    const int nt  = blockDim.x;
    for (int i = tid; i < 6 * 3 * 16; i += nt) s_mw1[i] = mw1[i];
    for (int i = tid; i < 6 * 16;     i += nt) s_mb1[i] = mb1[i];
    for (int i = tid; i < 6 * 16 * 32; i += nt) s_mw2[i] = mw2[i];
    for (int i = tid; i < 6 * 32;     i += nt) s_mb2[i] = mb2[i];
    for (int i = tid; i < 32 * 64;    i += nt) {
        int c = i >> 6, m = i & 63;            // ww1[c][m] -> s_w1t[m][c]
        s_w1t[m * 32 + c] = ww1[i];
    }
    for (int i = tid; i < 64;         i += nt) s_wb1[i] = wb1[i];
    for (int i = tid; i < 64 * 32;    i += nt) s_w2[i] = ww2[i];
    for (int i = tid; i < 32;         i += nt) s_wb2[i] = wb2[i];
    __syncthreads();

    const int p = blockIdx.x * nt + tid;
    if (p >= P) return;

    const float cx = center[p * 3 + 0];
    const float cy = center[p * 3 + 1];
    const float cz = center[p * 3 + 2];

    float q[32];
    mlp3_16_32(s_mw1 + 0 * 48, s_mb1 + 0 * 16, s_mw2 + 0 * 512, s_mb2 + 0 * 32,
               cx, cy, cz, q);

    float acc[32];
#pragma unroll
    for (int c = 0; c < 32; c++) acc[c] = 0.f;

#pragma unroll 1
    for (int j = 0; j <= KNB; j++) {
        float x0, x1, x2;
        int wk, wv;
        if (j == 0) {                          // center acts as its own neighbor
            x0 = cx; x1 = cy; x2 = cz; wk = 1; wv = 2;
        } else {
            const float* o = other + (p * KNB + (j - 1)) * 3;
            x0 = o[0]; x1 = o[1]; x2 = o[2]; wk = 3; wv = 4;
        }

        // pos = MLP5(center - x)
        float pos[32];
        mlp3_16_32(s_mw1 + 5 * 48, s_mb1 + 5 * 16, s_mw2 + 5 * 512, s_mb2 + 5 * 32,
                   cx - x0, cy - x1, cz - x2, pos);

        // v + pos
        float vpp[32];
        mlp3_16_32(s_mw1 + wv * 48, s_mb1 + wv * 16, s_mw2 + wv * 512, s_mb2 + wv * 32,
                   x0, x1, x2, vpp);
#pragma unroll
        for (int c = 0; c < 32; c++) vpp[c] += pos[c];

        // u = q - k + pos
        float u[32];
        mlp3_16_32(s_mw1 + wk * 48, s_mb1 + wk * 16, s_mw2 + wk * 512, s_mb2 + wk * 32,
                   x0, x1, x2, u);
#pragma unroll
        for (int c = 0; c < 32; c++) u[c] = q[c] - u[c] + pos[c];

        // weight_process: 32 -> 64 (leaky) -> 32, m-loop rolled & fused
        float w[32];
#pragma unroll
        for (int c = 0; c < 32; c++) w[c] = s_wb2[c];
#pragma unroll 1
        for (int m = 0; m < 64; m++) {
            float hh = s_wb1[m];
            const float* w1r = s_w1t + m * 32;
#pragma unroll
            for (int c = 0; c < 32; c++) hh += u[c] * w1r[c];
            hh = hh > 0.f ? hh : 0.01f * hh;
            const float* w2r = s_w2 + m * 32;
#pragma unroll
            for (int c = 0; c < 32; c++) w[c] += hh * w2r[c];
        }

        // softmax over channels, multiply by (v+pos), accumulate over neighbors
        float mx = w[0];
#pragma unroll
        for (int c = 1; c < 32; c++) mx = fmaxf(mx, w[c]);
        float ssum = 0.f;
#pragma unroll
        for (int c = 0; c < 32; c++) {
            float e = __expf(w[c] - mx);
            w[c] = e;
            ssum += e;
        }
        const float inv = __frcp_rn(ssum);
#pragma unroll
        for (int c = 0; c < 32; c++) acc[c] += w[c] * inv * vpp[c];
    }

#pragma unroll
    for (int c = 0; c < 32; c++) out[p * 32 + c] = acc[c];
}

extern "C" void kernel_launch(void* const* d_in, const int* in_sizes, int n_in,
                              void* d_out, int out_size)
{
    const float* center = (const float*)d_in[0];
    const float* other  = (const float*)d_in[1];
    const float* mw1    = (const float*)d_in[2];
    const float* mb1    = (const float*)d_in[3];
    const float* mw2    = (const float*)d_in[4];
    const float* mb2    = (const float*)d_in[5];
    const float* ww1    = (const float*)d_in[6];
    const float* wb1    = (const float*)d_in[7];
    const float* ww2    = (const float*)d_in[8];
    const float* wb2    = (const float*)d_in[9];
    float* out = (float*)d_out;

    const int P = in_sizes[0] / 3;
    const int block = 128;
    const int grid = (P + block - 1) / block;
    pae_kernel<<<grid, block>>>(center, other, mw1, mb1, mw2, mb2,
                                ww1, wb1, ww2, wb2, out, P);
}

// round 5
// speedup vs baseline: 1.1594x; 1.1594x over previous
#include <cuda_runtime.h>

// PointAttentionEncoder1D, packed-f32x2 version.
// P points, K=16 neighbors; 6x MLP(3->16->32, leaky 0.01), WP 32->64->32.
// Vector attention: softmax over channels, sum over neighbors.
// Strategy: 1 thread/point, weights in shared (LDS.128, broadcast),
// all 32-channel math as f32x2 packed FMA (fma.rn.f32x2).

typedef unsigned long long u64;
constexpr int KNB = 16;

__device__ __forceinline__ u64 pack2(float lo, float hi) {
    u64 r; asm("mov.b64 %0, {%1,%2};" : "=l"(r) : "f"(lo), "f"(hi)); return r;
}
__device__ __forceinline__ void unpack2(u64 v, float& lo, float& hi) {
    asm("mov.b64 {%0,%1}, %2;" : "=f"(lo), "=f"(hi) : "l"(v));
}
__device__ __forceinline__ u64 fma2(u64 a, u64 b, u64 c) {
    u64 d; asm("fma.rn.f32x2 %0, %1, %2, %3;" : "=l"(d) : "l"(a), "l"(b), "l"(c)); return d;
}
__device__ __forceinline__ u64 add2(u64 a, u64 b) {
    u64 d; asm("add.rn.f32x2 %0, %1, %2;" : "=l"(d) : "l"(a), "l"(b)); return d;
}
__device__ __forceinline__ u64 neg2(u64 a) { return a ^ 0x8000000080000000ULL; }

// MLP 3 -> 16 (leaky 0.01) -> 32, fully packed. o[16] holds 32 channels.
__device__ __forceinline__ void mlp2(
    const float* __restrict__ w1,   // [3][16] shared
    const float* __restrict__ b1,   // [16]
    const float* __restrict__ w2,   // [16][32]
    const float* __restrict__ b2,   // [32]
    float x0, float x1, float x2,
    u64* __restrict__ o)            // [16] packed channel pairs
{
    const u64 X0 = pack2(x0, x0), X1 = pack2(x1, x1), X2 = pack2(x2, x2);
    u64 hb[16];                     // hidden units, each broadcast-packed
#pragma unroll
    for (int i = 0; i < 16; i += 2) {
        u64 a = *(const u64*)(b1 + i);
        a = fma2(X0, *(const u64*)(w1 + i),      a);
        a = fma2(X1, *(const u64*)(w1 + 16 + i), a);
        a = fma2(X2, *(const u64*)(w1 + 32 + i), a);
        float va, vb; unpack2(a, va, vb);
        va = va > 0.f ? va : 0.01f * va;
        vb = vb > 0.f ? vb : 0.01f * vb;
        hb[i]     = pack2(va, va);
        hb[i + 1] = pack2(vb, vb);
    }
    {
        const ulonglong2* b2v = (const ulonglong2*)b2;
#pragma unroll
        for (int c = 0; c < 8; c++) { ulonglong2 t = b2v[c]; o[2*c] = t.x; o[2*c+1] = t.y; }
    }
#pragma unroll
    for (int i = 0; i < 16; i++) {
        const ulonglong2* w2r = (const ulonglong2*)(w2 + i * 32);
        const u64 hi2 = hb[i];
#pragma unroll
        for (int c = 0; c < 8; c++) {
            ulonglong2 t = w2r[c];
            o[2*c]   = fma2(hi2, t.x, o[2*c]);
            o[2*c+1] = fma2(hi2, t.y, o[2*c+1]);
        }
    }
}

__global__ void __launch_bounds__(128, 2)
pae_kernel(const float* __restrict__ center,   // [P,1,3]
           const float* __restrict__ other,    // [P,K,3]
           const float* __restrict__ mw1,      // [6,3,16]
           const float* __restrict__ mb1,      // [6,16]
           const float* __restrict__ mw2,      // [6,16,32]
           const float* __restrict__ mb2,      // [6,32]
           const float* __restrict__ ww1,      // [32,64]
           const float* __restrict__ wb1,      // [64]
           const float* __restrict__ ww2,      // [64,32]
           const float* __restrict__ wb2,      // [32]
           float* __restrict__ out,            // [P,32]
           int P)
{
    __shared__ __align__(16) float s_mw1[6 * 48];
    __shared__ __align__(16) float s_mb1[6 * 16];
    __shared__ __align__(16) float s_mw2[6 * 512];
    __shared__ __align__(16) float s_mb2[6 * 32];
    __shared__ __align__(16) float s_w1t[64 * 32];   // wp_w1 transposed: [m][c]
    __shared__ __align__(16) float s_wb1[64];
    __shared__ __align__(16) float s_w2[64 * 32];    // wp_w2: [m][c]
    __shared__ __align__(16) float s_wb2[32];

    const int tid = threadIdx.x;
    const int nt  = blockDim.x;
    for (int i = tid; i < 6 * 48;  i += nt) s_mw1[i] = mw1[i];
    for (int i = tid; i < 6 * 16;  i += nt) s_mb1[i] = mb1[i];
    for (int i = tid; i < 6 * 512; i += nt) s_mw2[i] = mw2[i];
    for (int i = tid; i < 6 * 32;  i += nt) s_mb2[i] = mb2[i];
    for (int i = tid; i < 32 * 64; i += nt) {
        int c = i >> 6, m = i & 63;                  // ww1[c][m] -> s_w1t[m][c]
        s_w1t[m * 32 + c] = ww1[i];
    }
    for (int i = tid; i < 64;      i += nt) s_wb1[i] = wb1[i];
    for (int i = tid; i < 64 * 32; i += nt) s_w2[i] = ww2[i];
    for (int i = tid; i < 32;      i += nt) s_wb2[i] = wb2[i];
    __syncthreads();

    const int p = blockIdx.x * nt + tid;
    if (p >= P) return;

    const float cx = center[p * 3 + 0];
    const float cy = center[p * 3 + 1];
    const float cz = center[p * 3 + 2];

    u64 q2[16];
    mlp2(s_mw1, s_mb1, s_mw2, s_mb2, cx, cy, cz, q2);

    u64 acc2[16];
#pragma unroll
    for (int c = 0; c < 16; c++) acc2[c] = 0ULL;     // (0.f, 0.f)

#pragma unroll 1
    for (int j = 0; j <= KNB; j++) {
        float x0, x1, x2;
        int kb, vb;
        if (j == 0) { x0 = cx; x1 = cy; x2 = cz; kb = 1; vb = 2; }
        else {
            const float* o = other + (p * KNB + (j - 1)) * 3;
            x0 = o[0]; x1 = o[1]; x2 = o[2]; kb = 3; vb = 4;
        }

        // pos = MLP5(center - x)
        u64 pos2[16];
        mlp2(s_mw1 + 5*48, s_mb1 + 5*16, s_mw2 + 5*512, s_mb2 + 5*32,
             cx - x0, cy - x1, cz - x2, pos2);

        // u = q - k + pos
        u64 u2[16];
        mlp2(s_mw1 + kb*48, s_mb1 + kb*16, s_mw2 + kb*512, s_mb2 + kb*32,
             x0, x1, x2, u2);
#pragma unroll
        for (int c = 0; c < 16; c++)
            u2[c] = add2(add2(q2[c], pos2[c]), neg2(u2[c]));

        // vpp = v + pos
        u64 vpp2[16];
        mlp2(s_mw1 + vb*48, s_mb1 + vb*16, s_mw2 + vb*512, s_mb2 + vb*32,
             x0, x1, x2, vpp2);
#pragma unroll
        for (int c = 0; c < 16; c++) vpp2[c] = add2(vpp2[c], pos2[c]);

        // weight_process: 32 -> 64 (leaky) -> 32, packed, m-loop rolled
        u64 w2a[16];
        {
            const ulonglong2* bb = (const ulonglong2*)s_wb2;
#pragma unroll
            for (int c = 0; c < 8; c++) { ulonglong2 t = bb[c]; w2a[2*c] = t.x; w2a[2*c+1] = t.y; }
        }
#pragma unroll 2
        for (int m = 0; m < 64; m++) {
            const ulonglong2* w1r = (const ulonglong2*)(s_w1t + m * 32);
            u64 s0 = 0ULL, s1 = 0ULL;
#pragma unroll
            for (int c = 0; c < 8; c++) {
                ulonglong2 t = w1r[c];
                s0 = fma2(u2[2*c],     t.x, s0);
                s1 = fma2(u2[2*c + 1], t.y, s1);
            }
            s0 = add2(s0, s1);
            float ha, hbv; unpack2(s0, ha, hbv);
            float hh = ha + hbv + s_wb1[m];
            hh = hh > 0.f ? hh : 0.01f * hh;
            const u64 hb2 = pack2(hh, hh);
            const ulonglong2* w2r = (const ulonglong2*)(s_w2 + m * 32);
#pragma unroll
            for (int c = 0; c < 8; c++) {
                ulonglong2 t = w2r[c];
                w2a[2*c]   = fma2(hb2, t.x, w2a[2*c]);
                w2a[2*c+1] = fma2(hb2, t.y, w2a[2*c+1]);
            }
        }

        // softmax over 32 channels; acc += softmax(w) * vpp
        float wf[32];
#pragma unroll
        for (int c = 0; c < 16; c++) unpack2(w2a[c], wf[2*c], wf[2*c+1]);
        float mx = wf[0];
#pragma unroll
        for (int c = 1; c < 32; c++) mx = fmaxf(mx, wf[c]);
        float ssum = 0.f;
#pragma unroll
        for (int c = 0; c < 32; c++) { float e = __expf(wf[c] - mx); wf[c] = e; ssum += e; }
        const float inv = __frcp_rn(ssum);
#pragma unroll
        for (int c = 0; c < 16; c++) {
            u64 e2 = pack2(wf[2*c] * inv, wf[2*c+1] * inv);
            acc2[c] = fma2(e2, vpp2[c], acc2[c]);
        }
    }

    // store [32] floats as 8x STG.128
    ulonglong2* op = (ulonglong2*)(out + p * 32);
#pragma unroll
    for (int c = 0; c < 8; c++) {
        ulonglong2 t; t.x = acc2[2*c]; t.y = acc2[2*c+1];
        op[c] = t;
    }
}

extern "C" void kernel_launch(void* const* d_in, const int* in_sizes, int n_in,
                              void* d_out, int out_size)
{
    const float* center = (const float*)d_in[0];
    const float* other  = (const float*)d_in[1];
    const float* mw1    = (const float*)d_in[2];
    const float* mb1    = (const float*)d_in[3];
    const float* mw2    = (const float*)d_in[4];
    const float* mb2    = (const float*)d_in[5];
    const float* ww1    = (const float*)d_in[6];
    const float* wb1    = (const float*)d_in[7];
    const float* ww2    = (const float*)d_in[8];
    const float* wb2    = (const float*)d_in[9];
    float* out = (float*)d_out;

    const int P = in_sizes[0] / 3;
    const int block = 128;
    const int grid = (P + block - 1) / block;
    pae_kernel<<<grid, block>>>(center, other, mw1, mb1, mw2, mb2,
                                ww1, wb1, ww2, wb2, out, P);
}

// round 6
// speedup vs baseline: 1.5927x; 1.3738x over previous
#include <cuda_runtime.h>

// PointAttentionEncoder1D — 2 threads per point, 16 channels each, f32x2 packed.
// P points, K=16 neighbors; 6x MLP(3->16->32, leaky 0.01), WP 32->64->32.
// Vector attention: softmax over channels, weighted sum over neighbors.

typedef unsigned long long u64;
constexpr int KNB = 16;

__device__ __forceinline__ u64 pack2(float lo, float hi) {
    u64 r; asm("mov.b64 %0, {%1,%2};" : "=l"(r) : "f"(lo), "f"(hi)); return r;
}
__device__ __forceinline__ void unpack2(u64 v, float& lo, float& hi) {
    asm("mov.b64 {%0,%1}, %2;" : "=f"(lo), "=f"(hi) : "l"(v));
}
__device__ __forceinline__ u64 fma2(u64 a, u64 b, u64 c) {
    u64 d; asm("fma.rn.f32x2 %0, %1, %2, %3;" : "=l"(d) : "l"(a), "l"(b), "l"(c)); return d;
}
__device__ __forceinline__ u64 add2(u64 a, u64 b) {
    u64 d; asm("add.rn.f32x2 %0, %1, %2;" : "=l"(d) : "l"(a), "l"(b)); return d;
}
__device__ __forceinline__ u64 neg2(u64 a) { return a ^ 0x8000000080000000ULL; }
__device__ __forceinline__ float leaky(float v) { return fmaxf(v, 0.01f * v); }

// MLP 3 -> 16 (leaky) -> 32, but this thread only produces its 16-channel half.
// w2h must already point at  (w2 base + 16*half); row stride stays 32.
__device__ __forceinline__ void mlp_half(
    const float* __restrict__ w1,   // [3][16] shared (full)
    const float* __restrict__ b1,   // [16]
    const float* __restrict__ w2h,  // [16][32] + 16*half
    const float* __restrict__ b2h,  // [32] + 16*half
    float x0, float x1, float x2,
    u64* __restrict__ o)            // [8] packed pairs = 16 channels
{
    const u64 X0 = pack2(x0, x0), X1 = pack2(x1, x1), X2 = pack2(x2, x2);
    float h[16];
#pragma unroll
    for (int i = 0; i < 8; i++) {
        u64 a = *(const u64*)(b1 + 2 * i);
        a = fma2(X0, *(const u64*)(w1 + 2 * i),      a);
        a = fma2(X1, *(const u64*)(w1 + 16 + 2 * i), a);
        a = fma2(X2, *(const u64*)(w1 + 32 + 2 * i), a);
        float va, vb; unpack2(a, va, vb);
        h[2 * i]     = leaky(va);
        h[2 * i + 1] = leaky(vb);
    }
    {
        const ulonglong2* bb = (const ulonglong2*)b2h;
#pragma unroll
        for (int c = 0; c < 4; c++) { ulonglong2 t = bb[c]; o[2*c] = t.x; o[2*c+1] = t.y; }
    }
#pragma unroll
    for (int i = 0; i < 16; i++) {
        const u64 h2 = pack2(h[i], h[i]);
        const ulonglong2* w2r = (const ulonglong2*)(w2h + i * 32);
#pragma unroll
        for (int c = 0; c < 4; c++) {
            ulonglong2 t = w2r[c];
            o[2*c]   = fma2(h2, t.x, o[2*c]);
            o[2*c+1] = fma2(h2, t.y, o[2*c+1]);
        }
    }
}

__global__ void __launch_bounds__(128, 4)
pae_kernel(const float* __restrict__ center,   // [P,1,3]
           const float* __restrict__ other,    // [P,K,3]
           const float* __restrict__ mw1,      // [6,3,16]
           const float* __restrict__ mb1,      // [6,16]
           const float* __restrict__ mw2,      // [6,16,32]
           const float* __restrict__ mb2,      // [6,32]
           const float* __restrict__ ww1,      // [32,64]
           const float* __restrict__ wb1,      // [64]
           const float* __restrict__ ww2,      // [64,32]
           const float* __restrict__ wb2,      // [32]
           float* __restrict__ out,            // [P,32]
           int P)
{
    __shared__ __align__(16) float s_mw1[6 * 48];
    __shared__ __align__(16) float s_mb1[6 * 16];
    __shared__ __align__(16) float s_mw2[6 * 512];
    __shared__ __align__(16) float s_mb2[6 * 32];
    __shared__ __align__(16) float s_w1t[64 * 32];   // wp_w1 transposed: [m][c]
    __shared__ __align__(16) float s_wb1[64];
    __shared__ __align__(16) float s_w2[64 * 32];    // wp_w2: [m][c]
    __shared__ __align__(16) float s_wb2[32];

    const int tid = threadIdx.x;
    const int nt  = blockDim.x;
    for (int i = tid; i < 6 * 48;  i += nt) s_mw1[i] = mw1[i];
    for (int i = tid; i < 6 * 16;  i += nt) s_mb1[i] = mb1[i];
    for (int i = tid; i < 6 * 512; i += nt) s_mw2[i] = mw2[i];
    for (int i = tid; i < 6 * 32;  i += nt) s_mb2[i] = mb2[i];
    for (int i = tid; i < 32 * 64; i += nt) {
        int c = i >> 6, m = i & 63;                  // ww1[c][m] -> s_w1t[m][c]
        s_w1t[m * 32 + c] = ww1[i];
    }
    for (int i = tid; i < 64;      i += nt) s_wb1[i] = wb1[i];
    for (int i = tid; i < 64 * 32; i += nt) s_w2[i] = ww2[i];
    for (int i = tid; i < 32;      i += nt) s_wb2[i] = wb2[i];
    __syncthreads();

    const int g = blockIdx.x * nt + tid;
    if (g >= 2 * P) return;
    const int p    = g >> 1;
    const int half = g & 1;
    const int co   = 16 * half;                      // channel offset of this half

    const float cx = center[p * 3 + 0];
    const float cy = center[p * 3 + 1];
    const float cz = center[p * 3 + 2];

    u64 q2[8];
    mlp_half(s_mw1, s_mb1, s_mw2 + co, s_mb2 + co, cx, cy, cz, q2);

    u64 acc2[8];
#pragma unroll
    for (int c = 0; c < 8; c++) acc2[c] = 0ULL;

#pragma unroll 1
    for (int j = 0; j <= KNB; j++) {
        float x0, x1, x2;
        int kb, vb;
        if (j == 0) { x0 = cx; x1 = cy; x2 = cz; kb = 1; vb = 2; }
        else {
            const float* o = other + (p * KNB + (j - 1)) * 3;
            x0 = o[0]; x1 = o[1]; x2 = o[2]; kb = 3; vb = 4;
        }

        // pos = MLP5(center - x)
        u64 pos2[8];
        mlp_half(s_mw1 + 5*48, s_mb1 + 5*16, s_mw2 + 5*512 + co, s_mb2 + 5*32 + co,
                 cx - x0, cy - x1, cz - x2, pos2);

        // u = q - k + pos
        u64 u2[8];
        mlp_half(s_mw1 + kb*48, s_mb1 + kb*16, s_mw2 + kb*512 + co, s_mb2 + kb*32 + co,
                 x0, x1, x2, u2);
#pragma unroll
        for (int c = 0; c < 8; c++)
            u2[c] = add2(add2(q2[c], pos2[c]), neg2(u2[c]));

        // weight_process 32 -> 64 (leaky) -> 32; this half does 16-ch partial dots,
        // pair-shfl completes the 32-wide layer-1 reduction.
        u64 wacc[8];
        {
            const ulonglong2* bb = (const ulonglong2*)(s_wb2 + co);
#pragma unroll
            for (int c = 0; c < 4; c++) { ulonglong2 t = bb[c]; wacc[2*c] = t.x; wacc[2*c+1] = t.y; }
        }
#pragma unroll 2
        for (int m = 0; m < 64; m++) {
            const ulonglong2* w1r = (const ulonglong2*)(s_w1t + m * 32 + co);
            u64 s0 = 0ULL, s1 = 0ULL;
#pragma unroll
            for (int c = 0; c < 4; c++) {
                ulonglong2 t = w1r[c];
                s0 = fma2(u2[2*c],     t.x, s0);
                s1 = fma2(u2[2*c + 1], t.y, s1);
            }
            s0 = add2(s0, s1);
            float pa, pb; unpack2(s0, pa, pb);
            float part = pa + pb;
            part += __shfl_xor_sync(0xffffffffu, part, 1);
            float hh = leaky(part + s_wb1[m]);
            const u64 h2 = pack2(hh, hh);
            const ulonglong2* w2r = (const ulonglong2*)(s_w2 + m * 32 + co);
#pragma unroll
            for (int c = 0; c < 4; c++) {
                ulonglong2 t = w2r[c];
                wacc[2*c]   = fma2(h2, t.x, wacc[2*c]);
                wacc[2*c+1] = fma2(h2, t.y, wacc[2*c+1]);
            }
        }

        // softmax over all 32 channels (16 local + pair-shfl for max/sum)
        float wf[16];
#pragma unroll
        for (int c = 0; c < 8; c++) unpack2(wacc[c], wf[2*c], wf[2*c+1]);
        float mx = wf[0];
#pragma unroll
        for (int c = 1; c < 16; c++) mx = fmaxf(mx, wf[c]);
        mx = fmaxf(mx, __shfl_xor_sync(0xffffffffu, mx, 1));
        float ssum = 0.f;
#pragma unroll
        for (int c = 0; c < 16; c++) { float e = __expf(wf[c] - mx); wf[c] = e; ssum += e; }
        ssum += __shfl_xor_sync(0xffffffffu, ssum, 1);
        const float inv = __frcp_rn(ssum);

        u64 e2[8];
#pragma unroll
        for (int c = 0; c < 8; c++)
            e2[c] = pack2(wf[2*c] * inv, wf[2*c+1] * inv);

        // acc += e * pos   (pos dead afterwards)
#pragma unroll
        for (int c = 0; c < 8; c++) acc2[c] = fma2(e2[c], pos2[c], acc2[c]);

        // v-MLP into temp, then acc += e * v
        u64 vt[8];
        mlp_half(s_mw1 + vb*48, s_mb1 + vb*16, s_mw2 + vb*512 + co, s_mb2 + vb*32 + co,
                 x0, x1, x2, vt);
#pragma unroll
        for (int c = 0; c < 8; c++) acc2[c] = fma2(e2[c], vt[c], acc2[c]);
    }

    // store this half's 16 floats (4x STG.128), coalesced across the pair
    ulonglong2* op = (ulonglong2*)(out + p * 32 + co);
#pragma unroll
    for (int c = 0; c < 4; c++) {
        ulonglong2 t; t.x = acc2[2*c]; t.y = acc2[2*c+1];
        op[c] = t;
    }
}

extern "C" void kernel_launch(void* const* d_in, const int* in_sizes, int n_in,
                              void* d_out, int out_size)
{
    const float* center = (const float*)d_in[0];
    const float* other  = (const float*)d_in[1];
    const float* mw1    = (const float*)d_in[2];
    const float* mb1    = (const float*)d_in[3];
    const float* mw2    = (const float*)d_in[4];
    const float* mb2    = (const float*)d_in[5];
    const float* ww1    = (const float*)d_in[6];
    const float* wb1    = (const float*)d_in[7];
    const float* ww2    = (const float*)d_in[8];
    const float* wb2    = (const float*)d_in[9];
    float* out = (float*)d_out;

    const int P = in_sizes[0] / 3;
    const int block = 128;
    const int grid = (2 * P + block - 1) / block;
    pae_kernel<<<grid, block>>>(center, other, mw1, mb1, mw2, mb2,
                                ww1, wb1, ww2, wb2, out, P);
}